// round 9
// baseline (speedup 1.0000x reference)
#include <cuda_runtime.h>

#define C_IN   512
#define IH     38
#define IW     50
#define HWPIX  1900
#define NANCH  17100
#define NSORT  32768
#define PRE_N  6000
#define POST_N 300
#define MASKW  94        // ceil(6000/64)

typedef unsigned long long ull;

// ---------------- device scratch (static, no allocation) ----------------
__device__ float    g_h1T[HWPIX * 512];                // conv partial (c 0..255)
__device__ float    g_h1T2[HWPIX * 512];               // conv partial (c 256..511)
__device__ float    g_box[NANCH * 4];                  // decoded clipped boxes
__device__ ull      g_keys[NSORT];                     // ping buffer
__device__ ull      g_keys2[NSORT];                    // pong buffer
__device__ float    g_tb[PRE_N * 4];                   // top-6000 boxes (sorted)
__device__ ull      g_mask[(size_t)PRE_N * MASKW];     // lower tri never written
__device__ ull      g_validw[96];                      // validity bits of top-6000
__device__ unsigned g_bar;                             // grid spin barrier

__constant__ float c_ab[9][4] = {
  {-37.254833f,  -82.50967f,   53.254833f,  98.50967f},
  {-82.50967f,  -173.01933f,   98.50967f,  189.01933f},
  {-173.01933f, -354.03867f,  189.01933f,  370.03867f},
  {-56.0f,       -56.0f,        72.0f,       72.0f},
  {-120.0f,     -120.0f,       136.0f,      136.0f},
  {-248.0f,     -248.0f,       264.0f,      264.0f},
  {-82.50967f,   -37.254833f,  98.50967f,   53.254833f},
  {-173.01933f,  -82.50967f,  189.01933f,   98.50967f},
  {-354.03867f, -173.01933f,  370.03867f,  189.01933f}};

// ---------------- f32x2 helpers ----------------
__device__ __forceinline__ void fma2(ull& d, ull a, ull b) {
  asm("fma.rn.f32x2 %0, %1, %2, %0;" : "+l"(d) : "l"(a), "l"(b));
}
__device__ __forceinline__ float2 unpk(ull v) {
  float2 f; asm("mov.b64 {%0, %1}, %2;" : "=f"(f.x), "=f"(f.y) : "l"(v)); return f;
}

// --- 3x3 conv partials, split-K x2, double-buffered, dup-x smem ---------
// grid (7,5,16): z = kt*2 + chalf. Each block: 64 k x 64 px x 256 c.
// dynamic smem: sW[2][72*66] floats | sXd[2][8][10][12] float2 (dup lanes)
#define SW_BUF  4752
#define SXD_BUF 960
__global__ __launch_bounds__(256) void conv3x3_relu(
    const float* __restrict__ x, const float* __restrict__ wgt) {
  extern __shared__ float smem_dyn[];
  float* sW = smem_dyn;                                   // [2][4752]
  float2* sXd = (float2*)(smem_dyn + 2 * SW_BUF);         // [2][960]

  const int wt = blockIdx.x;            // 0..6
  const int ht = blockIdx.y;            // 0..4
  const int kt = blockIdx.z >> 1;       // 0..7
  const int ch = blockIdx.z & 1;        // k-split half
  const int h0 = ht * 8, w0 = wt * 8;
  const int tid = threadIdx.x;
  const int ty  = tid >> 4;             // 0..15 (k groups of 4)
  const int txp = tid & 15;
  const int hh  = txp >> 1;             // 0..7
  const int wq  = txp & 1;              // 0..1 (w groups of 4)
  const int c_begin = ch * 256;

  ull a00 = 0, a01 = 0, a02 = 0, a03 = 0;
  ull a10 = 0, a11 = 0, a12 = 0, a13 = 0;

  const int k0g = kt * 64;

  // per-thread static load indices
  int wk[18], wcrs[18];
#pragma unroll
  for (int l = 0; l < 18; ++l) {
    int idx = tid + l * 256;            // = k*72 + crs
    wk[l] = idx / 72; wcrs[l] = idx % 72;
  }
  int xc[4], xrow[4], xcol[4], xoff[4];
  bool xon[4];
#pragma unroll
  for (int m = 0; m < 4; ++m) {
    int idx = tid + m * 256;
    xon[m] = idx < 800;
    int c = idx / 100, rem = idx % 100;
    xc[m] = c; xrow[m] = rem / 10; xcol[m] = rem % 10;
    xoff[m] = (c * 10 + xrow[m]) * 12 + xcol[m];
  }

  // prologue: fill buffer 0 for c0 = c_begin
  {
#pragma unroll
    for (int l = 0; l < 18; ++l)
      sW[wcrs[l] * 66 + wk[l]] =
          wgt[(size_t)(k0g + wk[l]) * 4608 + (size_t)c_begin * 9 + wcrs[l]];
#pragma unroll
    for (int m = 0; m < 4; ++m) {
      if (xon[m]) {
        int gh = h0 - 1 + xrow[m], gw = w0 - 1 + xcol[m];
        float v = 0.f;
        if (gh >= 0 && gh < IH && gw >= 0 && gw < IW)
          v = x[(size_t)(c_begin + xc[m]) * HWPIX + gh * IW + gw];
        sXd[xoff[m]] = make_float2(v, v);
      }
    }
  }
  __syncthreads();

  for (int cc = 0; cc < 256; cc += 8) {
    const int c0 = c_begin + cc;
    const int cur = (cc >> 3) & 1;
    const int nxt = cur ^ 1;
    const bool more = (cc + 8) < 256;

    // ---- stage next iteration's data into registers -------------------
    float wreg[18];
    float xreg[4];
    if (more) {
      const int c1 = c0 + 8;
#pragma unroll
      for (int l = 0; l < 18; ++l)
        wreg[l] = wgt[(size_t)(k0g + wk[l]) * 4608 + (size_t)c1 * 9 + wcrs[l]];
#pragma unroll
      for (int m = 0; m < 4; ++m) {
        float v = 0.f;
        if (xon[m]) {
          int gh = h0 - 1 + xrow[m], gw = w0 - 1 + xcol[m];
          if (gh >= 0 && gh < IH && gw >= 0 && gw < IW)
            v = x[(size_t)(c1 + xc[m]) * HWPIX + gh * IW + gw];
        }
        xreg[m] = v;
      }
    }

    // ---- compute from buf[cur] (same accumulation order) --------------
    const float* sWc = sW + cur * SW_BUF;
    const float2* sXc = sXd + cur * SXD_BUF;
#pragma unroll
    for (int c = 0; c < 8; ++c) {
#pragma unroll
      for (int r = 0; r < 3; ++r) {
        const float2* xp = &sXc[(c * 10 + (hh + r)) * 12 + wq * 4];
        ulonglong2 u0 = ((const ulonglong2*)xp)[0];
        ulonglong2 u1 = ((const ulonglong2*)xp)[1];
        ulonglong2 u2 = ((const ulonglong2*)xp)[2];
        ull xd[6] = {u0.x, u0.y, u1.x, u1.y, u2.x, u2.y};
#pragma unroll
        for (int s = 0; s < 3; ++s) {
          int wi = (c * 9 + r * 3 + s) * 66 + ty * 4;
          ull w01 = *(const ull*)&sWc[wi];
          ull w23 = *(const ull*)&sWc[wi + 2];
          fma2(a00, w01, xd[s + 0]);
          fma2(a01, w01, xd[s + 1]);
          fma2(a02, w01, xd[s + 2]);
          fma2(a03, w01, xd[s + 3]);
          fma2(a10, w23, xd[s + 0]);
          fma2(a11, w23, xd[s + 1]);
          fma2(a12, w23, xd[s + 2]);
          fma2(a13, w23, xd[s + 3]);
        }
      }
    }

    // ---- drain staged registers into the other buffer, single sync ----
    if (more) {
#pragma unroll
      for (int l = 0; l < 18; ++l)
        sW[nxt * SW_BUF + wcrs[l] * 66 + wk[l]] = wreg[l];
#pragma unroll
      for (int m = 0; m < 4; ++m)
        if (xon[m]) sXd[nxt * SXD_BUF + xoff[m]] = make_float2(xreg[m], xreg[m]);
    }
    __syncthreads();
  }

  // epilogue: raw partial store (bias+relu applied in rpn_head)
  const int h = h0 + hh;
  if (h < IH) {
    float* dst = ch ? g_h1T2 : g_h1T;
    float2 p0[4] = {unpk(a00), unpk(a01), unpk(a02), unpk(a03)};
    float2 p1[4] = {unpk(a10), unpk(a11), unpk(a12), unpk(a13)};
#pragma unroll
    for (int j = 0; j < 4; ++j) {
      int ww = w0 + wq * 4 + j;
      if (ww < IW) {
        int p = h * IW + ww;
        float4 o;
        o.x = p0[j].x; o.y = p0[j].y; o.z = p1[j].x; o.w = p1[j].y;
        *(float4*)(&dst[(size_t)p * 512 + k0g + ty * 4]) = o;
      }
    }
  }
}

// ------- 1x1 heads (4 px/block): partial-sum + bias + relu + decode -----
__device__ __forceinline__ unsigned f2key(float f) {
  unsigned u = __float_as_uint(f);
  return (u & 0x80000000u) ? ~u : (u | 0x80000000u);
}

__global__ __launch_bounds__(256) void rpn_head(
    const float* __restrict__ loc_w, const float* __restrict__ loc_b,
    const float* __restrict__ score_w, const float* __restrict__ score_b,
    const float* __restrict__ conv_b) {
  const int pb = blockIdx.x;            // 0..474 (4 pixels each)
  const int tid = threadIdx.x;
  if (pb == 0 && tid == 0) g_bar = 0u;  // reset grid barrier for fused_sort
  __shared__ float sh[4][512];
  __shared__ float sums[4][48];
  const int p0 = pb * 4;

#pragma unroll
  for (int m = 0; m < 4; ++m) {
    int idx = tid + m * 256;
    int px = idx >> 8, off = idx & 255;
    float2 a  = ((const float2*)(g_h1T  + (size_t)(p0 + px) * 512))[off];
    float2 b2 = ((const float2*)(g_h1T2 + (size_t)(p0 + px) * 512))[off];
    float2 bb = ((const float2*)conv_b)[off];
    float2 o;
    o.x = fmaxf(a.x + b2.x + bb.x, 0.f);
    o.y = fmaxf(a.y + b2.y + bb.y, 0.f);
    ((float2*)sh[px])[off] = o;
  }
  __syncthreads();

  const int wid = tid >> 5, lane = tid & 31;
  for (int o = wid; o < 45; o += 8) {
    const float* wrow;
    float bb;
    if (o < 36) { wrow = loc_w + (size_t)o * 512; bb = loc_b[o]; }
    else { int a = o - 36; wrow = score_w + (size_t)(2 * a + 1) * 512; bb = score_b[2 * a + 1]; }
    float s0 = 0.f, s1 = 0.f, s2 = 0.f, s3 = 0.f;
#pragma unroll 4
    for (int c = lane; c < 512; c += 32) {
      float wv = wrow[c];
      s0 = fmaf(wv, sh[0][c], s0);
      s1 = fmaf(wv, sh[1][c], s1);
      s2 = fmaf(wv, sh[2][c], s2);
      s3 = fmaf(wv, sh[3][c], s3);
    }
#pragma unroll
    for (int off = 16; off; off >>= 1) {
      s0 += __shfl_down_sync(0xffffffffu, s0, off);
      s1 += __shfl_down_sync(0xffffffffu, s1, off);
      s2 += __shfl_down_sync(0xffffffffu, s2, off);
      s3 += __shfl_down_sync(0xffffffffu, s3, off);
    }
    if (lane == 0) {
      sums[0][o] = s0 + bb; sums[1][o] = s1 + bb;
      sums[2][o] = s2 + bb; sums[3][o] = s3 + bb;
    }
  }
  __syncthreads();

  if (tid < 36) {
    const int px = tid / 9, a = tid % 9;
    const int p = p0 + px;
    float dy = sums[px][a * 4 + 0], dx = sums[px][a * 4 + 1];
    float dh = sums[px][a * 4 + 2], dw = sums[px][a * 4 + 3];
    float fg = sums[px][36 + a];
    int h = p / IW, w = p % IW;
    float sy = (float)h * 16.f, sx = (float)w * 16.f;
    float ay0 = __fadd_rn(sy, c_ab[a][0]);
    float ax0 = __fadd_rn(sx, c_ab[a][1]);
    float ay1 = __fadd_rn(sy, c_ab[a][2]);
    float ax1 = __fadd_rn(sx, c_ab[a][3]);
    float ah = __fadd_rn(ay1, -ay0);
    float aw = __fadd_rn(ax1, -ax0);
    float acy = __fadd_rn(ay0, __fmul_rn(0.5f, ah));
    float acx = __fadd_rn(ax0, __fmul_rn(0.5f, aw));
    float cy = __fadd_rn(__fmul_rn(dy, ah), acy);
    float cx = __fadd_rn(__fmul_rn(dx, aw), acx);
    float bh = __fmul_rn(expf(dh), ah);
    float bw = __fmul_rn(expf(dw), aw);
    float y1 = fminf(fmaxf(__fadd_rn(cy, -__fmul_rn(0.5f, bh)), 0.f), 608.f);
    float x1 = fminf(fmaxf(__fadd_rn(cx, -__fmul_rn(0.5f, bw)), 0.f), 800.f);
    float y2 = fminf(fmaxf(__fadd_rn(cy,  __fmul_rn(0.5f, bh)), 0.f), 608.f);
    float x2 = fminf(fmaxf(__fadd_rn(cx,  __fmul_rn(0.5f, bw)), 0.f), 800.f);
    bool valid = (__fadd_rn(y2, -y1) >= 16.f) && (__fadd_rn(x2, -x1) >= 16.f);
    float sc = valid ? fg : -__int_as_float(0x7f800000);

    int i = p * 9 + a;
    g_box[i * 4 + 0] = y1; g_box[i * 4 + 1] = x1;
    g_box[i * 4 + 2] = y2; g_box[i * 4 + 3] = x2;
    g_keys[i] = ((ull)f2key(sc) << 32) | (ull)(~(unsigned)i);
  }
}

// ---------------- fused bitonic sort (8 persistent blocks) --------------
__device__ __forceinline__ void grid_sync(unsigned& target) {
  __syncthreads();
  target += 8;
  if (threadIdx.x == 0) {
    __threadfence();
    atomicAdd(&g_bar, 1u);
    while (atomicAdd(&g_bar, 0u) < target) {}
    __threadfence();
  }
  __syncthreads();
}

__global__ __launch_bounds__(1024) void fused_sort() {
  __shared__ ull s[4096];
  const int base = blockIdx.x * 4096;
  const int t = threadIdx.x;
  unsigned bar_t = 0;

#pragma unroll
  for (int m = 0; m < 4; ++m) {
    int l = t + m * 1024, e = base + l;
    s[l] = (e < NANCH) ? g_keys[e] : 0ull;
  }
  __syncthreads();

  for (int k = 2; k <= 4096; k <<= 1) {
    for (int j = k >> 1; j > 0; j >>= 1) {
#pragma unroll
      for (int m = 0; m < 2; ++m) {
        int tt = t + m * 1024;
        int i = ((tt & ~(j - 1)) << 1) | (tt & (j - 1));
        int ix = i | j;
        bool desc = (((base + i) & k) == 0);
        ull a = s[i], b = s[ix];
        if (desc ? (a < b) : (a > b)) { s[i] = b; s[ix] = a; }
      }
      __syncthreads();
    }
  }

#define STORE_TO(buf) do {                                   \
    _Pragma("unroll")                                        \
    for (int m = 0; m < 4; ++m)                              \
      (buf)[base + t + m * 1024] = s[t + m * 1024];          \
  } while (0)

#define COMBINE(buf, K, J) do {                              \
    bool lower = ((base & (J)) == 0);                        \
    bool descC = ((base & (K)) == 0);                        \
    bool takeMax = (lower == descC);                         \
    _Pragma("unroll")                                        \
    for (int m = 0; m < 4; ++m) {                            \
      int l = t + m * 1024;                                  \
      ull v = __ldcg(&(buf)[(base + l) ^ (J)]);              \
      ull mv = s[l];                                         \
      s[l] = takeMax ? (mv > v ? mv : v) : (mv < v ? mv : v);\
    }                                                        \
    __syncthreads();                                         \
  } while (0)

#define TAIL(K) do {                                         \
    bool descT = ((base & (K)) == 0);                        \
    for (int j = 2048; j > 0; j >>= 1) {                     \
      _Pragma("unroll")                                      \
      for (int m = 0; m < 2; ++m) {                          \
        int tt = t + m * 1024;                               \
        int i = ((tt & ~(j - 1)) << 1) | (tt & (j - 1));     \
        int ix = i | j;                                      \
        ull a = s[i], b = s[ix];                             \
        if (descT ? (a < b) : (a > b)) { s[i] = b; s[ix] = a; } \
      }                                                      \
      __syncthreads();                                       \
    }                                                        \
  } while (0)

  STORE_TO(g_keys);  grid_sync(bar_t);
  COMBINE(g_keys, 8192, 4096);  TAIL(8192);

  STORE_TO(g_keys2); grid_sync(bar_t);
  COMBINE(g_keys2, 16384, 8192);

  STORE_TO(g_keys);  grid_sync(bar_t);
  COMBINE(g_keys, 16384, 4096);  TAIL(16384);

  STORE_TO(g_keys2); grid_sync(bar_t);
  COMBINE(g_keys2, 32768, 16384);

  STORE_TO(g_keys);  grid_sync(bar_t);
  COMBINE(g_keys, 32768, 8192);

  STORE_TO(g_keys2); grid_sync(bar_t);
  COMBINE(g_keys2, 32768, 4096);  TAIL(32768);

  if (base < 6144) {
#pragma unroll
    for (int m = 0; m < 4; ++m) {
      int l = t + m * 1024, e = base + l;
      if (e < 6144) {
        ull key = s[l];
        bool valid = (e < PRE_N) && ((unsigned)(key >> 32) > 0x007FFFFFu);
        unsigned bal = __ballot_sync(0xffffffffu, valid);
        if ((t & 31) == 0) ((unsigned*)g_validw)[e >> 5] = bal;
        if (e < PRE_N) {
          unsigned idx = ~(unsigned)(key & 0xffffffffull);
          float4 b = make_float4(0.f, 0.f, 0.f, 0.f);
          if (idx < NANCH) b = ((const float4*)g_box)[idx];
          ((float4*)g_tb)[e] = b;
        }
      }
    }
  }
#undef STORE_TO
#undef COMBINE
#undef TAIL
}

// ------- NMS mask: 128-row x 64-col tiles, fully unrolled inner ---------
__global__ __launch_bounds__(128) void nms_mask() {
  const int cb = blockIdx.x;      // 0..93
  const int rb = blockIdx.y;      // 0..46
  if (cb < 2 * rb) return;
  const int tid = threadIdx.x;
  __shared__ float4 colb[64];
  __shared__ float cola[64];
  const int j0 = cb * 64;
  if (tid < 64) {
    int jj = j0 + tid;
    float4 b = (jj < PRE_N) ? ((const float4*)g_tb)[jj]
                            : make_float4(0.f, 0.f, 0.f, 0.f);
    colb[tid] = b;
    cola[tid] = __fmul_rn(__fadd_rn(b.z, -b.x), __fadd_rn(b.w, -b.y));
  }
  __syncthreads();
  const int i = rb * 128 + tid;
  if (i >= PRE_N) return;
  if (i >= j0 + 64) return;
  float4 r = ((const float4*)g_tb)[i];
  float ra = __fmul_rn(__fadd_rn(r.z, -r.x), __fadd_rn(r.w, -r.y));
  ull bits = 0ull;
#pragma unroll
  for (int q = 0; q < 64; ++q) {
    float4 c = colb[q];
    float ty1 = fmaxf(r.x, c.x);
    float tx1 = fmaxf(r.y, c.y);
    float ty2 = fminf(r.z, c.z);
    float tx2 = fminf(r.w, c.w);
    float ihh = fmaxf(__fadd_rn(ty2, -ty1), 0.f);
    float iww = fmaxf(__fadd_rn(tx2, -tx1), 0.f);
    float inter = __fmul_rn(ihh, iww);
    float uni = fmaxf(__fadd_rn(__fadd_rn(ra, cola[q]), -inter), 1e-9f);
    float d = __fmaf_rn(-0.7f, uni, inter);
    bool sup;
    if (fabsf(d) < 3e-5f * uni)
      sup = (__fdiv_rn(inter, uni) > 0.7f);
    else
      sup = d > 0.f;
    if (sup) bits |= (1ull << q);
  }
  if (j0 <= i) {
    int dq = i - j0;
    bits = (dq >= 63) ? 0ull : (bits & (~0ull << (dq + 1)));
  }
  g_mask[(size_t)i * MASKW + cb] = bits;
}

// ---- NMS scan: ffs bit-walk + parallel row fold, early stop @300 -------
__global__ __launch_bounds__(256) void nms_scan(float* __restrict__ out) {
  __shared__ ull remv[MASKW];
  __shared__ int keptIdx[POST_N];
  __shared__ int wordKept[64];
  __shared__ int s_nk, s_nwk;
  const int tid = threadIdx.x;
  if (tid < MASKW) remv[tid] = 0ull;
  if (tid == 0) s_nk = 0;
  for (int i = tid; i < POST_N * 4; i += 256) out[i] = 0.f;
  __syncthreads();

  for (int w = 0; w < MASKW; ++w) {
    if (tid < 32) {
      ull vw = g_validw[w];
      ull alive = vw & ~remv[w];
      int base = w * 64;
      ull mA = ((alive >> tid) & 1ull) ? g_mask[(size_t)(base + tid) * MASKW + w] : 0ull;
      ull mB = ((alive >> (tid + 32)) & 1ull) ? g_mask[(size_t)(base + tid + 32) * MASKW + w] : 0ull;
      int nk = s_nk, nwk = 0;
      while (alive && nk < POST_N) {
        int q = __ffsll((long long)alive) - 1;
        ull mq = (q < 32) ? __shfl_sync(0xffffffffu, mA, q)
                          : __shfl_sync(0xffffffffu, mB, q - 32);
        if (tid == 0) { keptIdx[nk] = base + q; wordKept[nwk] = base + q; }
        ++nk; ++nwk;
        alive &= ~((1ull << q) | mq);
      }
      if (tid == 0) { s_nk = nk; s_nwk = nwk; }
    }
    __syncthreads();
    int total = s_nwk * MASKW;
    for (int e = tid; e < total; e += 256) {
      int r = e / MASKW, wd = e - r * MASKW;
      ull m = g_mask[(size_t)wordKept[r] * MASKW + wd];
      if (m) atomicOr(&remv[wd], m);
    }
    __syncthreads();
    if (s_nk >= POST_N) break;
  }

  __syncthreads();
  for (int r = tid; r < s_nk; r += 256)
    ((float4*)out)[r] = ((const float4*)g_tb)[keptIdx[r]];
}

// ---------------- launcher ----------------
extern "C" void kernel_launch(void* const* d_in, const int* in_sizes, int n_in,
                              void* d_out, int out_size) {
  const float* x        = (const float*)d_in[0];
  const float* conv1_w  = (const float*)d_in[1];
  const float* conv1_b  = (const float*)d_in[2];
  const float* loc_w    = (const float*)d_in[3];
  const float* loc_b    = (const float*)d_in[4];
  const float* score_w  = (const float*)d_in[5];
  const float* score_b  = (const float*)d_in[6];
  float* out = (float*)d_out;

  const int CONV_SMEM = (2 * SW_BUF + 2 * SXD_BUF * 2) * 4;  // 53376 bytes
  static bool attr_done = false;
  if (!attr_done) {
    cudaFuncSetAttribute(conv3x3_relu,
                         cudaFuncAttributeMaxDynamicSharedMemorySize, CONV_SMEM);
    attr_done = true;
  }

  dim3 cgrid(7, 5, 16);
  conv3x3_relu<<<cgrid, 256, CONV_SMEM>>>(x, conv1_w);
  rpn_head<<<475, 256>>>(loc_w, loc_b, score_w, score_b, conv1_b);
  fused_sort<<<8, 1024>>>();
  nms_mask<<<dim3(94, 47), 128>>>();
  nms_scan<<<1, 256>>>(out);
}

// round 10
// speedup vs baseline: 1.0688x; 1.0688x over previous
#include <cuda_runtime.h>

#define C_IN   512
#define IH     38
#define IW     50
#define HWPIX  1900
#define NANCH  17100
#define NSORT  32768
#define PRE_N  6000
#define POST_N 300
#define MASKW  94        // ceil(6000/64)
#define NTILES 2256      // live upper-triangle 128x64 tiles

typedef unsigned long long ull;

// ---------------- device scratch (static, no allocation) ----------------
__device__ float    g_h1T[HWPIX * 512];                // conv output, [pixel][k]
__device__ float    g_box[NANCH * 4];                  // decoded clipped boxes
__device__ ull      g_keys[NSORT];                     // ping buffer
__device__ ull      g_keys2[NSORT];                    // pong buffer
__device__ float    g_tb[PRE_N * 4];                   // top-6000 boxes (sorted)
__device__ ull      g_mask[(size_t)PRE_N * MASKW];     // lower tri never written
__device__ ull      g_validw[96];                      // validity bits of top-6000
__device__ unsigned g_bar;                             // sort grid barrier
__device__ unsigned g_bar2;                            // mask/scan grid barrier

__constant__ float c_ab[9][4] = {
  {-37.254833f,  -82.50967f,   53.254833f,  98.50967f},
  {-82.50967f,  -173.01933f,   98.50967f,  189.01933f},
  {-173.01933f, -354.03867f,  189.01933f,  370.03867f},
  {-56.0f,       -56.0f,        72.0f,       72.0f},
  {-120.0f,     -120.0f,       136.0f,      136.0f},
  {-248.0f,     -248.0f,       264.0f,      264.0f},
  {-82.50967f,   -37.254833f,  98.50967f,   53.254833f},
  {-173.01933f,  -82.50967f,  189.01933f,   98.50967f},
  {-354.03867f, -173.01933f,  370.03867f,  189.01933f}};

// ---------------- f32x2 helpers ----------------
__device__ __forceinline__ ull dup2(float v) {
  ull r; asm("mov.b64 %0, {%1, %1};" : "=l"(r) : "f"(v)); return r;
}
__device__ __forceinline__ void fma2(ull& d, ull a, ull b) {
  asm("fma.rn.f32x2 %0, %1, %2, %0;" : "+l"(d) : "l"(a), "l"(b));
}
__device__ __forceinline__ float2 unpk(ull v) {
  float2 f; asm("mov.b64 {%0, %1}, %2;" : "=f"(f.x), "=f"(f.y) : "l"(v)); return f;
}

// ------- 3x3 conv + bias + relu, double-buffered + reg-staged prefetch --
__global__ __launch_bounds__(256) void conv3x3_relu(
    const float* __restrict__ x, const float* __restrict__ wgt,
    const float* __restrict__ bias) {
  const int wt = blockIdx.x;            // 0..6
  const int ht = blockIdx.y;            // 0..4
  const int kt = blockIdx.z;            // 0..7
  const int h0 = ht * 8, w0 = wt * 8;
  const int tid = threadIdx.x;
  const int ty  = tid >> 4;             // 0..15 (k groups of 4)
  const int txp = tid & 15;
  const int hh  = txp >> 1;             // 0..7
  const int wq  = txp & 1;              // 0..1 (w groups of 4)

  __shared__ float sW[2][72 * 66];                  // [buf][crs*66+k]
  __shared__ __align__(16) float sX[2][8][10][12];  // [buf][c][row][col]

  ull a00 = 0, a01 = 0, a02 = 0, a03 = 0;
  ull a10 = 0, a11 = 0, a12 = 0, a13 = 0;

  const int k0g = kt * 64;

  int wk[18], wcrs[18];
#pragma unroll
  for (int l = 0; l < 18; ++l) {
    int idx = tid + l * 256;            // = k*72 + crs
    wk[l] = idx / 72; wcrs[l] = idx % 72;
  }
  int xc[4], xrow[4], xcol[4];
  bool xon[4];
#pragma unroll
  for (int m = 0; m < 4; ++m) {
    int idx = tid + m * 256;
    xon[m] = idx < 800;
    int c = idx / 100, rem = idx % 100;
    xc[m] = c; xrow[m] = rem / 10; xcol[m] = rem % 10;
  }

  // prologue: fill buffer 0 for c0=0
  {
#pragma unroll
    for (int l = 0; l < 18; ++l)
      sW[0][wcrs[l] * 66 + wk[l]] =
          wgt[(size_t)(k0g + wk[l]) * 4608 + wcrs[l]];
#pragma unroll
    for (int m = 0; m < 4; ++m) {
      if (xon[m]) {
        int gh = h0 - 1 + xrow[m], gw = w0 - 1 + xcol[m];
        float v = 0.f;
        if (gh >= 0 && gh < IH && gw >= 0 && gw < IW)
          v = x[(size_t)xc[m] * HWPIX + gh * IW + gw];
        sX[0][xc[m]][xrow[m]][xcol[m]] = v;
      }
    }
  }
  __syncthreads();

  for (int c0 = 0; c0 < C_IN; c0 += 8) {
    const int cur = (c0 >> 3) & 1;
    const int nxt = cur ^ 1;
    const bool more = (c0 + 8) < C_IN;

    float wreg[18];
    float xreg[4];
    if (more) {
      const int c1 = c0 + 8;
#pragma unroll
      for (int l = 0; l < 18; ++l)
        wreg[l] = wgt[(size_t)(k0g + wk[l]) * 4608 + (size_t)c1 * 9 + wcrs[l]];
#pragma unroll
      for (int m = 0; m < 4; ++m) {
        float v = 0.f;
        if (xon[m]) {
          int gh = h0 - 1 + xrow[m], gw = w0 - 1 + xcol[m];
          if (gh >= 0 && gh < IH && gw >= 0 && gw < IW)
            v = x[(size_t)(c1 + xc[m]) * HWPIX + gh * IW + gw];
        }
        xreg[m] = v;
      }
    }

    const float* sWc = sW[cur];
#pragma unroll
    for (int c = 0; c < 8; ++c) {
#pragma unroll
      for (int r = 0; r < 3; ++r) {
        const float* xp = &sX[cur][c][hh + r][wq * 4];
        float4 xa = *(const float4*)xp;
        float2 xb = *(const float2*)(xp + 4);
        ull xd[6] = {dup2(xa.x), dup2(xa.y), dup2(xa.z),
                     dup2(xa.w), dup2(xb.x), dup2(xb.y)};
#pragma unroll
        for (int s = 0; s < 3; ++s) {
          int wi = (c * 9 + r * 3 + s) * 66 + ty * 4;
          ull w01 = *(const ull*)&sWc[wi];
          ull w23 = *(const ull*)&sWc[wi + 2];
          fma2(a00, w01, xd[s + 0]);
          fma2(a01, w01, xd[s + 1]);
          fma2(a02, w01, xd[s + 2]);
          fma2(a03, w01, xd[s + 3]);
          fma2(a10, w23, xd[s + 0]);
          fma2(a11, w23, xd[s + 1]);
          fma2(a12, w23, xd[s + 2]);
          fma2(a13, w23, xd[s + 3]);
        }
      }
    }

    if (more) {
#pragma unroll
      for (int l = 0; l < 18; ++l)
        sW[nxt][wcrs[l] * 66 + wk[l]] = wreg[l];
#pragma unroll
      for (int m = 0; m < 4; ++m)
        if (xon[m]) sX[nxt][xc[m]][xrow[m]][xcol[m]] = xreg[m];
    }
    __syncthreads();
  }

  const int h = h0 + hh;
  if (h < IH) {
    float b0 = bias[k0g + ty * 4 + 0];
    float b1 = bias[k0g + ty * 4 + 1];
    float b2 = bias[k0g + ty * 4 + 2];
    float b3 = bias[k0g + ty * 4 + 3];
    float2 p0[4] = {unpk(a00), unpk(a01), unpk(a02), unpk(a03)};
    float2 p1[4] = {unpk(a10), unpk(a11), unpk(a12), unpk(a13)};
#pragma unroll
    for (int j = 0; j < 4; ++j) {
      int ww = w0 + wq * 4 + j;
      if (ww < IW) {
        int p = h * IW + ww;
        float4 o;
        o.x = fmaxf(p0[j].x + b0, 0.f);
        o.y = fmaxf(p0[j].y + b1, 0.f);
        o.z = fmaxf(p1[j].x + b2, 0.f);
        o.w = fmaxf(p1[j].y + b3, 0.f);
        *(float4*)(&g_h1T[(size_t)p * 512 + k0g + ty * 4]) = o;
      }
    }
  }
}

// ------- 1x1 heads (4 pixels/block) + anchor decode + key build ---------
__device__ __forceinline__ unsigned f2key(float f) {
  unsigned u = __float_as_uint(f);
  return (u & 0x80000000u) ? ~u : (u | 0x80000000u);
}

__global__ __launch_bounds__(256) void rpn_head(
    const float* __restrict__ loc_w, const float* __restrict__ loc_b,
    const float* __restrict__ score_w, const float* __restrict__ score_b) {
  const int pb = blockIdx.x;            // 0..474 (4 pixels each)
  const int tid = threadIdx.x;
  if (pb == 0 && tid == 0) { g_bar = 0u; g_bar2 = 0u; }  // reset grid barriers
  __shared__ float sh[4][512];
  __shared__ float sums[4][48];
  const int p0 = pb * 4;

#pragma unroll
  for (int m = 0; m < 4; ++m) {
    int idx = tid + m * 256;
    int px = idx >> 8, off = idx & 255;
    ((float2*)sh[px])[off] =
        ((const float2*)(g_h1T + (size_t)(p0 + px) * 512))[off];
  }
  __syncthreads();

  const int wid = tid >> 5, lane = tid & 31;
  for (int o = wid; o < 45; o += 8) {
    const float* wrow;
    float bb;
    if (o < 36) { wrow = loc_w + (size_t)o * 512; bb = loc_b[o]; }
    else { int a = o - 36; wrow = score_w + (size_t)(2 * a + 1) * 512; bb = score_b[2 * a + 1]; }
    float s0 = 0.f, s1 = 0.f, s2 = 0.f, s3 = 0.f;
#pragma unroll 4
    for (int c = lane; c < 512; c += 32) {
      float wv = wrow[c];
      s0 = fmaf(wv, sh[0][c], s0);
      s1 = fmaf(wv, sh[1][c], s1);
      s2 = fmaf(wv, sh[2][c], s2);
      s3 = fmaf(wv, sh[3][c], s3);
    }
#pragma unroll
    for (int off = 16; off; off >>= 1) {
      s0 += __shfl_down_sync(0xffffffffu, s0, off);
      s1 += __shfl_down_sync(0xffffffffu, s1, off);
      s2 += __shfl_down_sync(0xffffffffu, s2, off);
      s3 += __shfl_down_sync(0xffffffffu, s3, off);
    }
    if (lane == 0) {
      sums[0][o] = s0 + bb; sums[1][o] = s1 + bb;
      sums[2][o] = s2 + bb; sums[3][o] = s3 + bb;
    }
  }
  __syncthreads();

  if (tid < 36) {
    const int px = tid / 9, a = tid % 9;
    const int p = p0 + px;
    float dy = sums[px][a * 4 + 0], dx = sums[px][a * 4 + 1];
    float dh = sums[px][a * 4 + 2], dw = sums[px][a * 4 + 3];
    float fg = sums[px][36 + a];
    int h = p / IW, w = p % IW;
    float sy = (float)h * 16.f, sx = (float)w * 16.f;
    float ay0 = __fadd_rn(sy, c_ab[a][0]);
    float ax0 = __fadd_rn(sx, c_ab[a][1]);
    float ay1 = __fadd_rn(sy, c_ab[a][2]);
    float ax1 = __fadd_rn(sx, c_ab[a][3]);
    float ah = __fadd_rn(ay1, -ay0);
    float aw = __fadd_rn(ax1, -ax0);
    float acy = __fadd_rn(ay0, __fmul_rn(0.5f, ah));
    float acx = __fadd_rn(ax0, __fmul_rn(0.5f, aw));
    float cy = __fadd_rn(__fmul_rn(dy, ah), acy);
    float cx = __fadd_rn(__fmul_rn(dx, aw), acx);
    float bh = __fmul_rn(expf(dh), ah);
    float bw = __fmul_rn(expf(dw), aw);
    float y1 = fminf(fmaxf(__fadd_rn(cy, -__fmul_rn(0.5f, bh)), 0.f), 608.f);
    float x1 = fminf(fmaxf(__fadd_rn(cx, -__fmul_rn(0.5f, bw)), 0.f), 800.f);
    float y2 = fminf(fmaxf(__fadd_rn(cy,  __fmul_rn(0.5f, bh)), 0.f), 608.f);
    float x2 = fminf(fmaxf(__fadd_rn(cx,  __fmul_rn(0.5f, bw)), 0.f), 800.f);
    bool valid = (__fadd_rn(y2, -y1) >= 16.f) && (__fadd_rn(x2, -x1) >= 16.f);
    float sc = valid ? fg : -__int_as_float(0x7f800000);

    int i = p * 9 + a;
    g_box[i * 4 + 0] = y1; g_box[i * 4 + 1] = x1;
    g_box[i * 4 + 2] = y2; g_box[i * 4 + 3] = x2;
    g_keys[i] = ((ull)f2key(sc) << 32) | (ull)(~(unsigned)i);
  }
}

// ---------------- fused bitonic sort (8 persistent blocks) --------------
__device__ __forceinline__ void grid_sync8(unsigned& target) {
  __syncthreads();
  target += 8;
  if (threadIdx.x == 0) {
    __threadfence();
    atomicAdd(&g_bar, 1u);
    while (atomicAdd(&g_bar, 0u) < target) {}
    __threadfence();
  }
  __syncthreads();
}

__global__ __launch_bounds__(1024) void fused_sort() {
  __shared__ ull s[4096];
  const int base = blockIdx.x * 4096;
  const int t = threadIdx.x;
  unsigned bar_t = 0;

#pragma unroll
  for (int m = 0; m < 4; ++m) {
    int l = t + m * 1024, e = base + l;
    s[l] = (e < NANCH) ? g_keys[e] : 0ull;
  }
  __syncthreads();

  for (int k = 2; k <= 4096; k <<= 1) {
    for (int j = k >> 1; j > 0; j >>= 1) {
#pragma unroll
      for (int m = 0; m < 2; ++m) {
        int tt = t + m * 1024;
        int i = ((tt & ~(j - 1)) << 1) | (tt & (j - 1));
        int ix = i | j;
        bool desc = (((base + i) & k) == 0);
        ull a = s[i], b = s[ix];
        if (desc ? (a < b) : (a > b)) { s[i] = b; s[ix] = a; }
      }
      __syncthreads();
    }
  }

#define STORE_TO(buf) do {                                   \
    _Pragma("unroll")                                        \
    for (int m = 0; m < 4; ++m)                              \
      (buf)[base + t + m * 1024] = s[t + m * 1024];          \
  } while (0)

#define COMBINE(buf, K, J) do {                              \
    bool lower = ((base & (J)) == 0);                        \
    bool descC = ((base & (K)) == 0);                        \
    bool takeMax = (lower == descC);                         \
    _Pragma("unroll")                                        \
    for (int m = 0; m < 4; ++m) {                            \
      int l = t + m * 1024;                                  \
      ull v = __ldcg(&(buf)[(base + l) ^ (J)]);              \
      ull mv = s[l];                                         \
      s[l] = takeMax ? (mv > v ? mv : v) : (mv < v ? mv : v);\
    }                                                        \
    __syncthreads();                                         \
  } while (0)

#define TAIL(K) do {                                         \
    bool descT = ((base & (K)) == 0);                        \
    for (int j = 2048; j > 0; j >>= 1) {                     \
      _Pragma("unroll")                                      \
      for (int m = 0; m < 2; ++m) {                          \
        int tt = t + m * 1024;                               \
        int i = ((tt & ~(j - 1)) << 1) | (tt & (j - 1));     \
        int ix = i | j;                                      \
        ull a = s[i], b = s[ix];                             \
        if (descT ? (a < b) : (a > b)) { s[i] = b; s[ix] = a; } \
      }                                                      \
      __syncthreads();                                       \
    }                                                        \
  } while (0)

  STORE_TO(g_keys);  grid_sync8(bar_t);
  COMBINE(g_keys, 8192, 4096);  TAIL(8192);

  STORE_TO(g_keys2); grid_sync8(bar_t);
  COMBINE(g_keys2, 16384, 8192);

  STORE_TO(g_keys);  grid_sync8(bar_t);
  COMBINE(g_keys, 16384, 4096);  TAIL(16384);

  STORE_TO(g_keys2); grid_sync8(bar_t);
  COMBINE(g_keys2, 32768, 16384);

  STORE_TO(g_keys);  grid_sync8(bar_t);
  COMBINE(g_keys, 32768, 8192);

  STORE_TO(g_keys2); grid_sync8(bar_t);

  // only blocks covering e < 8192 matter from here on
  if (base < 8192) {
    COMBINE(g_keys2, 32768, 4096);  TAIL(32768);
    // epilogue: gather boxes + validity ballots (only e < 6144 matters)
#pragma unroll
    for (int m = 0; m < 4; ++m) {
      int l = t + m * 1024, e = base + l;
      if (e < 6144) {
        ull key = s[l];
        bool valid = (e < PRE_N) && ((unsigned)(key >> 32) > 0x007FFFFFu);
        unsigned bal = __ballot_sync(0xffffffffu, valid);
        if ((t & 31) == 0) ((unsigned*)g_validw)[e >> 5] = bal;
        if (e < PRE_N) {
          unsigned idx = ~(unsigned)(key & 0xffffffffull);
          float4 b = make_float4(0.f, 0.f, 0.f, 0.f);
          if (idx < NANCH) b = ((const float4*)g_box)[idx];
          ((float4*)g_tb)[e] = b;
        }
      }
    }
  }
#undef STORE_TO
#undef COMBINE
#undef TAIL
}

// ------ fused NMS: persistent mask tiles + grid sync + block-0 scan -----
__global__ __launch_bounds__(128) void nms_mask_scan(float* __restrict__ out) {
  const int tid = threadIdx.x;
  const int bid = blockIdx.x;
  __shared__ float4 colb[64];
  __shared__ float cola[64];

  // block 0 zeroes the output while working its tiles
  if (bid == 0)
    for (int i = tid; i < POST_N * 4; i += 128) out[i] = 0.f;

  // ---- phase 1: mask tiles (live set: cb >= 2*rb) ----
  for (int tI = bid; tI < NTILES; tI += 148) {
    // decode tI -> (rb, cb)
    int rb = 0, rem = tI;
    while (rem >= MASKW - 2 * rb) { rem -= MASKW - 2 * rb; ++rb; }
    int cb = 2 * rb + rem;
    const int j0 = cb * 64;

    if (tid < 64) {
      int jj = j0 + tid;
      float4 b = (jj < PRE_N) ? ((const float4*)g_tb)[jj]
                              : make_float4(0.f, 0.f, 0.f, 0.f);
      colb[tid] = b;
      cola[tid] = __fmul_rn(__fadd_rn(b.z, -b.x), __fadd_rn(b.w, -b.y));
    }
    __syncthreads();

    const int i = rb * 128 + tid;
    if (i < PRE_N && i < j0 + 64) {
      float4 r = ((const float4*)g_tb)[i];
      float ra = __fmul_rn(__fadd_rn(r.z, -r.x), __fadd_rn(r.w, -r.y));
      ull bits = 0ull;
#pragma unroll
      for (int q = 0; q < 64; ++q) {
        float4 c = colb[q];
        float ty1 = fmaxf(r.x, c.x);
        float tx1 = fmaxf(r.y, c.y);
        float ty2 = fminf(r.z, c.z);
        float tx2 = fminf(r.w, c.w);
        float ihh = fmaxf(__fadd_rn(ty2, -ty1), 0.f);
        float iww = fmaxf(__fadd_rn(tx2, -tx1), 0.f);
        float inter = __fmul_rn(ihh, iww);
        float uni = fmaxf(__fadd_rn(__fadd_rn(ra, cola[q]), -inter), 1e-9f);
        float d = __fmaf_rn(-0.7f, uni, inter);
        bool sup;
        if (fabsf(d) < 3e-5f * uni)
          sup = (__fdiv_rn(inter, uni) > 0.7f);     // exact (matches reference)
        else
          sup = d > 0.f;
        if (sup) bits |= (1ull << q);
      }
      if (j0 <= i) {                  // diagonal tile: keep only cols > i
        int dq = i - j0;
        bits = (dq >= 63) ? 0ull : (bits & (~0ull << (dq + 1)));
      }
      g_mask[(size_t)i * MASKW + cb] = bits;
    }
    __syncthreads();                  // smem reuse across tiles
  }

  // ---- grid sync over all 148 blocks ----
  __syncthreads();
  if (tid == 0) {
    __threadfence();
    atomicAdd(&g_bar2, 1u);
    while (atomicAdd(&g_bar2, 0u) < 148u) {}
    __threadfence();
  }
  __syncthreads();

  if (bid != 0) return;

  // ---- phase 2: scan (block 0 only) ----
  __shared__ ull remv[MASKW];
  __shared__ int keptIdx[POST_N];
  __shared__ int wordKept[64];
  __shared__ int s_nk, s_nwk;
  if (tid < MASKW) remv[tid] = 0ull;
  if (tid == 0) s_nk = 0;
  __syncthreads();

  for (int w = 0; w < MASKW; ++w) {
    if (tid < 32) {
      ull vw = g_validw[w];
      ull alive = vw & ~remv[w];
      int base = w * 64;
      ull mA = ((alive >> tid) & 1ull) ? g_mask[(size_t)(base + tid) * MASKW + w] : 0ull;
      ull mB = ((alive >> (tid + 32)) & 1ull) ? g_mask[(size_t)(base + tid + 32) * MASKW + w] : 0ull;
      int nk = s_nk, nwk = 0;
      while (alive && nk < POST_N) {
        int q = __ffsll((long long)alive) - 1;
        ull mq = (q < 32) ? __shfl_sync(0xffffffffu, mA, q)
                          : __shfl_sync(0xffffffffu, mB, q - 32);
        if (tid == 0) { keptIdx[nk] = base + q; wordKept[nwk] = base + q; }
        ++nk; ++nwk;
        alive &= ~((1ull << q) | mq);
      }
      if (tid == 0) { s_nk = nk; s_nwk = nwk; }
    }
    __syncthreads();                  // publishes s_nk/s_nwk/wordKept
    if (s_nwk > 0) {
      int total = s_nwk * MASKW;
      for (int e = tid; e < total; e += 128) {
        int r = e / MASKW, wd = e - r * MASKW;
        ull m = g_mask[(size_t)wordKept[r] * MASKW + wd];
        if (m) atomicOr(&remv[wd], m);
      }
      __syncthreads();                // publishes remv
    }
    if (s_nk >= POST_N) break;
  }

  __syncthreads();
  for (int r = tid; r < s_nk; r += 128)
    ((float4*)out)[r] = ((const float4*)g_tb)[keptIdx[r]];
}

// ---------------- launcher ----------------
extern "C" void kernel_launch(void* const* d_in, const int* in_sizes, int n_in,
                              void* d_out, int out_size) {
  const float* x        = (const float*)d_in[0];
  const float* conv1_w  = (const float*)d_in[1];
  const float* conv1_b  = (const float*)d_in[2];
  const float* loc_w    = (const float*)d_in[3];
  const float* loc_b    = (const float*)d_in[4];
  const float* score_w  = (const float*)d_in[5];
  const float* score_b  = (const float*)d_in[6];
  float* out = (float*)d_out;

  dim3 cgrid(7, 5, 8);
  conv3x3_relu<<<cgrid, 256>>>(x, conv1_w, conv1_b);
  rpn_head<<<475, 256>>>(loc_w, loc_b, score_w, score_b);
  fused_sort<<<8, 1024>>>();
  nms_mask_scan<<<148, 128>>>(out);
}

// round 11
// speedup vs baseline: 1.3096x; 1.2253x over previous
#include <cuda_runtime.h>

#define C_IN   512
#define IH     38
#define IW     50
#define HWPIX  1900
#define NANCH  17100
#define NSORT  32768
#define PRE_N  6000
#define POST_N 300
#define MASKW  94        // ceil(6000/64)

typedef unsigned long long ull;

// ---------------- device scratch (static, no allocation) ----------------
__device__ float    g_h1T[HWPIX * 512];                // conv output, [pixel][k]
__device__ float    g_box[NANCH * 4];                  // decoded clipped boxes
__device__ ull      g_keys[NSORT];                     // ping buffer
__device__ ull      g_keys2[NSORT];                    // pong buffer
__device__ float    g_tb[PRE_N * 4];                   // top-6000 boxes (sorted)
__device__ ull      g_mask[(size_t)PRE_N * MASKW];     // lower tri never written
__device__ ull      g_validw[96];                      // validity bits of top-6000
__device__ unsigned g_bar;                             // sort grid barrier

__constant__ float c_ab[9][4] = {
  {-37.254833f,  -82.50967f,   53.254833f,  98.50967f},
  {-82.50967f,  -173.01933f,   98.50967f,  189.01933f},
  {-173.01933f, -354.03867f,  189.01933f,  370.03867f},
  {-56.0f,       -56.0f,        72.0f,       72.0f},
  {-120.0f,     -120.0f,       136.0f,      136.0f},
  {-248.0f,     -248.0f,       264.0f,      264.0f},
  {-82.50967f,   -37.254833f,  98.50967f,   53.254833f},
  {-173.01933f,  -82.50967f,  189.01933f,   98.50967f},
  {-354.03867f, -173.01933f,  370.03867f,  189.01933f}};

// ---------------- f32x2 helpers ----------------
__device__ __forceinline__ ull dup2(float v) {
  ull r; asm("mov.b64 %0, {%1, %1};" : "=l"(r) : "f"(v)); return r;
}
__device__ __forceinline__ void fma2(ull& d, ull a, ull b) {
  asm("fma.rn.f32x2 %0, %1, %2, %0;" : "+l"(d) : "l"(a), "l"(b));
}
__device__ __forceinline__ float2 unpk(ull v) {
  float2 f; asm("mov.b64 {%0, %1}, %2;" : "=f"(f.x), "=f"(f.y) : "l"(v)); return f;
}

// ------- 3x3 conv + bias + relu, double-buffered + reg-staged prefetch --
__global__ __launch_bounds__(256) void conv3x3_relu(
    const float* __restrict__ x, const float* __restrict__ wgt,
    const float* __restrict__ bias) {
  const int wt = blockIdx.x;            // 0..6
  const int ht = blockIdx.y;            // 0..4
  const int kt = blockIdx.z;            // 0..7
  const int h0 = ht * 8, w0 = wt * 8;
  const int tid = threadIdx.x;
  const int ty  = tid >> 4;             // 0..15 (k groups of 4)
  const int txp = tid & 15;
  const int hh  = txp >> 1;             // 0..7
  const int wq  = txp & 1;              // 0..1 (w groups of 4)

  __shared__ float sW[2][72 * 66];                  // [buf][crs*66+k]
  __shared__ __align__(16) float sX[2][8][10][12];  // [buf][c][row][col]

  ull a00 = 0, a01 = 0, a02 = 0, a03 = 0;
  ull a10 = 0, a11 = 0, a12 = 0, a13 = 0;

  const int k0g = kt * 64;

  int wk[18], wcrs[18];
#pragma unroll
  for (int l = 0; l < 18; ++l) {
    int idx = tid + l * 256;            // = k*72 + crs
    wk[l] = idx / 72; wcrs[l] = idx % 72;
  }
  int xc[4], xrow[4], xcol[4];
  bool xon[4];
#pragma unroll
  for (int m = 0; m < 4; ++m) {
    int idx = tid + m * 256;
    xon[m] = idx < 800;
    int c = idx / 100, rem = idx % 100;
    xc[m] = c; xrow[m] = rem / 10; xcol[m] = rem % 10;
  }

  // prologue: fill buffer 0 for c0=0
  {
#pragma unroll
    for (int l = 0; l < 18; ++l)
      sW[0][wcrs[l] * 66 + wk[l]] =
          wgt[(size_t)(k0g + wk[l]) * 4608 + wcrs[l]];
#pragma unroll
    for (int m = 0; m < 4; ++m) {
      if (xon[m]) {
        int gh = h0 - 1 + xrow[m], gw = w0 - 1 + xcol[m];
        float v = 0.f;
        if (gh >= 0 && gh < IH && gw >= 0 && gw < IW)
          v = x[(size_t)xc[m] * HWPIX + gh * IW + gw];
        sX[0][xc[m]][xrow[m]][xcol[m]] = v;
      }
    }
  }
  __syncthreads();

  for (int c0 = 0; c0 < C_IN; c0 += 8) {
    const int cur = (c0 >> 3) & 1;
    const int nxt = cur ^ 1;
    const bool more = (c0 + 8) < C_IN;

    float wreg[18];
    float xreg[4];
    if (more) {
      const int c1 = c0 + 8;
#pragma unroll
      for (int l = 0; l < 18; ++l)
        wreg[l] = wgt[(size_t)(k0g + wk[l]) * 4608 + (size_t)c1 * 9 + wcrs[l]];
#pragma unroll
      for (int m = 0; m < 4; ++m) {
        float v = 0.f;
        if (xon[m]) {
          int gh = h0 - 1 + xrow[m], gw = w0 - 1 + xcol[m];
          if (gh >= 0 && gh < IH && gw >= 0 && gw < IW)
            v = x[(size_t)(c1 + xc[m]) * HWPIX + gh * IW + gw];
        }
        xreg[m] = v;
      }
    }

    const float* sWc = sW[cur];
#pragma unroll
    for (int c = 0; c < 8; ++c) {
#pragma unroll
      for (int r = 0; r < 3; ++r) {
        const float* xp = &sX[cur][c][hh + r][wq * 4];
        float4 xa = *(const float4*)xp;
        float2 xb = *(const float2*)(xp + 4);
        ull xd[6] = {dup2(xa.x), dup2(xa.y), dup2(xa.z),
                     dup2(xa.w), dup2(xb.x), dup2(xb.y)};
#pragma unroll
        for (int s = 0; s < 3; ++s) {
          int wi = (c * 9 + r * 3 + s) * 66 + ty * 4;
          ull w01 = *(const ull*)&sWc[wi];
          ull w23 = *(const ull*)&sWc[wi + 2];
          fma2(a00, w01, xd[s + 0]);
          fma2(a01, w01, xd[s + 1]);
          fma2(a02, w01, xd[s + 2]);
          fma2(a03, w01, xd[s + 3]);
          fma2(a10, w23, xd[s + 0]);
          fma2(a11, w23, xd[s + 1]);
          fma2(a12, w23, xd[s + 2]);
          fma2(a13, w23, xd[s + 3]);
        }
      }
    }

    if (more) {
#pragma unroll
      for (int l = 0; l < 18; ++l)
        sW[nxt][wcrs[l] * 66 + wk[l]] = wreg[l];
#pragma unroll
      for (int m = 0; m < 4; ++m)
        if (xon[m]) sX[nxt][xc[m]][xrow[m]][xcol[m]] = xreg[m];
    }
    __syncthreads();
  }

  const int h = h0 + hh;
  if (h < IH) {
    float b0 = bias[k0g + ty * 4 + 0];
    float b1 = bias[k0g + ty * 4 + 1];
    float b2 = bias[k0g + ty * 4 + 2];
    float b3 = bias[k0g + ty * 4 + 3];
    float2 p0[4] = {unpk(a00), unpk(a01), unpk(a02), unpk(a03)};
    float2 p1[4] = {unpk(a10), unpk(a11), unpk(a12), unpk(a13)};
#pragma unroll
    for (int j = 0; j < 4; ++j) {
      int ww = w0 + wq * 4 + j;
      if (ww < IW) {
        int p = h * IW + ww;
        float4 o;
        o.x = fmaxf(p0[j].x + b0, 0.f);
        o.y = fmaxf(p0[j].y + b1, 0.f);
        o.z = fmaxf(p1[j].x + b2, 0.f);
        o.w = fmaxf(p1[j].y + b3, 0.f);
        *(float4*)(&g_h1T[(size_t)p * 512 + k0g + ty * 4]) = o;
      }
    }
  }
}

// ------- 1x1 heads (4 pixels/block) + anchor decode + key build ---------
__device__ __forceinline__ unsigned f2key(float f) {
  unsigned u = __float_as_uint(f);
  return (u & 0x80000000u) ? ~u : (u | 0x80000000u);
}

__global__ __launch_bounds__(256) void rpn_head(
    const float* __restrict__ loc_w, const float* __restrict__ loc_b,
    const float* __restrict__ score_w, const float* __restrict__ score_b) {
  const int pb = blockIdx.x;            // 0..474 (4 pixels each)
  const int tid = threadIdx.x;
  if (pb == 0 && tid == 0) g_bar = 0u;  // reset grid barrier for fused_sort
  __shared__ float sh[4][512];
  __shared__ float sums[4][48];
  const int p0 = pb * 4;

#pragma unroll
  for (int m = 0; m < 4; ++m) {
    int idx = tid + m * 256;
    int px = idx >> 8, off = idx & 255;
    ((float2*)sh[px])[off] =
        ((const float2*)(g_h1T + (size_t)(p0 + px) * 512))[off];
  }
  __syncthreads();

  const int wid = tid >> 5, lane = tid & 31;
  for (int o = wid; o < 45; o += 8) {
    const float* wrow;
    float bb;
    if (o < 36) { wrow = loc_w + (size_t)o * 512; bb = loc_b[o]; }
    else { int a = o - 36; wrow = score_w + (size_t)(2 * a + 1) * 512; bb = score_b[2 * a + 1]; }
    float s0 = 0.f, s1 = 0.f, s2 = 0.f, s3 = 0.f;
#pragma unroll 4
    for (int c = lane; c < 512; c += 32) {
      float wv = wrow[c];
      s0 = fmaf(wv, sh[0][c], s0);
      s1 = fmaf(wv, sh[1][c], s1);
      s2 = fmaf(wv, sh[2][c], s2);
      s3 = fmaf(wv, sh[3][c], s3);
    }
#pragma unroll
    for (int off = 16; off; off >>= 1) {
      s0 += __shfl_down_sync(0xffffffffu, s0, off);
      s1 += __shfl_down_sync(0xffffffffu, s1, off);
      s2 += __shfl_down_sync(0xffffffffu, s2, off);
      s3 += __shfl_down_sync(0xffffffffu, s3, off);
    }
    if (lane == 0) {
      sums[0][o] = s0 + bb; sums[1][o] = s1 + bb;
      sums[2][o] = s2 + bb; sums[3][o] = s3 + bb;
    }
  }
  __syncthreads();

  if (tid < 36) {
    const int px = tid / 9, a = tid % 9;
    const int p = p0 + px;
    float dy = sums[px][a * 4 + 0], dx = sums[px][a * 4 + 1];
    float dh = sums[px][a * 4 + 2], dw = sums[px][a * 4 + 3];
    float fg = sums[px][36 + a];
    int h = p / IW, w = p % IW;
    float sy = (float)h * 16.f, sx = (float)w * 16.f;
    float ay0 = __fadd_rn(sy, c_ab[a][0]);
    float ax0 = __fadd_rn(sx, c_ab[a][1]);
    float ay1 = __fadd_rn(sy, c_ab[a][2]);
    float ax1 = __fadd_rn(sx, c_ab[a][3]);
    float ah = __fadd_rn(ay1, -ay0);
    float aw = __fadd_rn(ax1, -ax0);
    float acy = __fadd_rn(ay0, __fmul_rn(0.5f, ah));
    float acx = __fadd_rn(ax0, __fmul_rn(0.5f, aw));
    float cy = __fadd_rn(__fmul_rn(dy, ah), acy);
    float cx = __fadd_rn(__fmul_rn(dx, aw), acx);
    float bh = __fmul_rn(expf(dh), ah);
    float bw = __fmul_rn(expf(dw), aw);
    float y1 = fminf(fmaxf(__fadd_rn(cy, -__fmul_rn(0.5f, bh)), 0.f), 608.f);
    float x1 = fminf(fmaxf(__fadd_rn(cx, -__fmul_rn(0.5f, bw)), 0.f), 800.f);
    float y2 = fminf(fmaxf(__fadd_rn(cy,  __fmul_rn(0.5f, bh)), 0.f), 608.f);
    float x2 = fminf(fmaxf(__fadd_rn(cx,  __fmul_rn(0.5f, bw)), 0.f), 800.f);
    bool valid = (__fadd_rn(y2, -y1) >= 16.f) && (__fadd_rn(x2, -x1) >= 16.f);
    float sc = valid ? fg : -__int_as_float(0x7f800000);

    int i = p * 9 + a;
    g_box[i * 4 + 0] = y1; g_box[i * 4 + 1] = x1;
    g_box[i * 4 + 2] = y2; g_box[i * 4 + 3] = x2;
    g_keys[i] = ((ull)f2key(sc) << 32) | (ull)(~(unsigned)i);
  }
}

// ---------------- fused bitonic sort (8 persistent blocks) --------------
__device__ __forceinline__ void grid_sync8(unsigned& target) {
  __syncthreads();
  target += 8;
  if (threadIdx.x == 0) {
    __threadfence();
    atomicAdd(&g_bar, 1u);
    while (atomicAdd(&g_bar, 0u) < target) {}
    __threadfence();
  }
  __syncthreads();
}

__global__ __launch_bounds__(1024) void fused_sort() {
  __shared__ ull s[4096];
  const int base = blockIdx.x * 4096;
  const int t = threadIdx.x;
  unsigned bar_t = 0;

#pragma unroll
  for (int m = 0; m < 4; ++m) {
    int l = t + m * 1024, e = base + l;
    s[l] = (e < NANCH) ? g_keys[e] : 0ull;
  }
  __syncthreads();

  for (int k = 2; k <= 4096; k <<= 1) {
    for (int j = k >> 1; j > 0; j >>= 1) {
#pragma unroll
      for (int m = 0; m < 2; ++m) {
        int tt = t + m * 1024;
        int i = ((tt & ~(j - 1)) << 1) | (tt & (j - 1));
        int ix = i | j;
        bool desc = (((base + i) & k) == 0);
        ull a = s[i], b = s[ix];
        if (desc ? (a < b) : (a > b)) { s[i] = b; s[ix] = a; }
      }
      __syncthreads();
    }
  }

#define STORE_TO(buf) do {                                   \
    _Pragma("unroll")                                        \
    for (int m = 0; m < 4; ++m)                              \
      (buf)[base + t + m * 1024] = s[t + m * 1024];          \
  } while (0)

#define COMBINE(buf, K, J) do {                              \
    bool lower = ((base & (J)) == 0);                        \
    bool descC = ((base & (K)) == 0);                        \
    bool takeMax = (lower == descC);                         \
    _Pragma("unroll")                                        \
    for (int m = 0; m < 4; ++m) {                            \
      int l = t + m * 1024;                                  \
      ull v = __ldcg(&(buf)[(base + l) ^ (J)]);              \
      ull mv = s[l];                                         \
      s[l] = takeMax ? (mv > v ? mv : v) : (mv < v ? mv : v);\
    }                                                        \
    __syncthreads();                                         \
  } while (0)

#define TAIL(K) do {                                         \
    bool descT = ((base & (K)) == 0);                        \
    for (int j = 2048; j > 0; j >>= 1) {                     \
      _Pragma("unroll")                                      \
      for (int m = 0; m < 2; ++m) {                          \
        int tt = t + m * 1024;                               \
        int i = ((tt & ~(j - 1)) << 1) | (tt & (j - 1));     \
        int ix = i | j;                                      \
        ull a = s[i], b = s[ix];                             \
        if (descT ? (a < b) : (a > b)) { s[i] = b; s[ix] = a; } \
      }                                                      \
      __syncthreads();                                       \
    }                                                        \
  } while (0)

  STORE_TO(g_keys);  grid_sync8(bar_t);
  COMBINE(g_keys, 8192, 4096);  TAIL(8192);

  STORE_TO(g_keys2); grid_sync8(bar_t);
  COMBINE(g_keys2, 16384, 8192);

  STORE_TO(g_keys);  grid_sync8(bar_t);
  COMBINE(g_keys, 16384, 4096);  TAIL(16384);

  STORE_TO(g_keys2); grid_sync8(bar_t);
  COMBINE(g_keys2, 32768, 16384);

  STORE_TO(g_keys);  grid_sync8(bar_t);
  COMBINE(g_keys, 32768, 8192);

  STORE_TO(g_keys2); grid_sync8(bar_t);

  // only blocks covering e < 8192 matter from here on (others' output unread)
  if (base < 8192) {
    COMBINE(g_keys2, 32768, 4096);  TAIL(32768);
    // epilogue: gather boxes + validity ballots (only e < 6144 matters)
#pragma unroll
    for (int m = 0; m < 4; ++m) {
      int l = t + m * 1024, e = base + l;
      if (e < 6144) {
        ull key = s[l];
        bool valid = (e < PRE_N) && ((unsigned)(key >> 32) > 0x007FFFFFu);
        unsigned bal = __ballot_sync(0xffffffffu, valid);
        if ((t & 31) == 0) ((unsigned*)g_validw)[e >> 5] = bal;
        if (e < PRE_N) {
          unsigned idx = ~(unsigned)(key & 0xffffffffull);
          float4 b = make_float4(0.f, 0.f, 0.f, 0.f);
          if (idx < NANCH) b = ((const float4*)g_box)[idx];
          ((float4*)g_tb)[e] = b;
        }
      }
    }
  }
#undef STORE_TO
#undef COMBINE
#undef TAIL
}

// ------- NMS mask: 128-row x 64-col tiles, fully unrolled inner ---------
__global__ __launch_bounds__(128) void nms_mask() {
  const int cb = blockIdx.x;      // 0..93
  const int rb = blockIdx.y;      // 0..46
  if (cb < 2 * rb) return;
  const int tid = threadIdx.x;
  __shared__ float4 colb[64];
  __shared__ float cola[64];
  const int j0 = cb * 64;
  if (tid < 64) {
    int jj = j0 + tid;
    float4 b = (jj < PRE_N) ? ((const float4*)g_tb)[jj]
                            : make_float4(0.f, 0.f, 0.f, 0.f);
    colb[tid] = b;
    cola[tid] = __fmul_rn(__fadd_rn(b.z, -b.x), __fadd_rn(b.w, -b.y));
  }
  __syncthreads();
  const int i = rb * 128 + tid;
  if (i >= PRE_N) return;
  if (i >= j0 + 64) return;
  float4 r = ((const float4*)g_tb)[i];
  float ra = __fmul_rn(__fadd_rn(r.z, -r.x), __fadd_rn(r.w, -r.y));
  ull bits = 0ull;
#pragma unroll
  for (int q = 0; q < 64; ++q) {
    float4 c = colb[q];
    float ty1 = fmaxf(r.x, c.x);
    float tx1 = fmaxf(r.y, c.y);
    float ty2 = fminf(r.z, c.z);
    float tx2 = fminf(r.w, c.w);
    float ihh = fmaxf(__fadd_rn(ty2, -ty1), 0.f);
    float iww = fmaxf(__fadd_rn(tx2, -tx1), 0.f);
    float inter = __fmul_rn(ihh, iww);
    float uni = fmaxf(__fadd_rn(__fadd_rn(ra, cola[q]), -inter), 1e-9f);
    float d = __fmaf_rn(-0.7f, uni, inter);
    bool sup;
    if (fabsf(d) < 3e-5f * uni)
      sup = (__fdiv_rn(inter, uni) > 0.7f);
    else
      sup = d > 0.f;
    if (sup) bits |= (1ull << q);
  }
  if (j0 <= i) {
    int dq = i - j0;
    bits = (dq >= 63) ? 0ull : (bits & (~0ull << (dq + 1)));
  }
  g_mask[(size_t)i * MASKW + cb] = bits;
}

// ---- NMS scan: ffs bit-walk + parallel row fold, early stop @300 -------
__global__ __launch_bounds__(256) void nms_scan(float* __restrict__ out) {
  __shared__ ull remv[MASKW];
  __shared__ int keptIdx[POST_N];
  __shared__ int wordKept[64];
  __shared__ int s_nk, s_nwk;
  const int tid = threadIdx.x;
  if (tid < MASKW) remv[tid] = 0ull;
  if (tid == 0) s_nk = 0;
  for (int i = tid; i < POST_N * 4; i += 256) out[i] = 0.f;
  __syncthreads();

  for (int w = 0; w < MASKW; ++w) {
    if (tid < 32) {
      ull vw = g_validw[w];
      ull alive = vw & ~remv[w];
      int base = w * 64;
      ull mA = ((alive >> tid) & 1ull) ? g_mask[(size_t)(base + tid) * MASKW + w] : 0ull;
      ull mB = ((alive >> (tid + 32)) & 1ull) ? g_mask[(size_t)(base + tid + 32) * MASKW + w] : 0ull;
      int nk = s_nk, nwk = 0;
      while (alive && nk < POST_N) {
        int q = __ffsll((long long)alive) - 1;
        ull mq = (q < 32) ? __shfl_sync(0xffffffffu, mA, q)
                          : __shfl_sync(0xffffffffu, mB, q - 32);
        if (tid == 0) { keptIdx[nk] = base + q; wordKept[nwk] = base + q; }
        ++nk; ++nwk;
        alive &= ~((1ull << q) | mq);
      }
      if (tid == 0) { s_nk = nk; s_nwk = nwk; }
    }
    __syncthreads();                  // publishes s_nk/s_nwk/wordKept
    if (s_nwk > 0) {                  // uniform: skip fold when nothing kept
      int total = s_nwk * MASKW;
      for (int e = tid; e < total; e += 256) {
        int r = e / MASKW, wd = e - r * MASKW;
        ull m = g_mask[(size_t)wordKept[r] * MASKW + wd];
        if (m) atomicOr(&remv[wd], m);
      }
      __syncthreads();                // publishes remv
    }
    if (s_nk >= POST_N) break;
  }

  __syncthreads();
  for (int r = tid; r < s_nk; r += 256)
    ((float4*)out)[r] = ((const float4*)g_tb)[keptIdx[r]];
}

// ---------------- launcher ----------------
extern "C" void kernel_launch(void* const* d_in, const int* in_sizes, int n_in,
                              void* d_out, int out_size) {
  const float* x        = (const float*)d_in[0];
  const float* conv1_w  = (const float*)d_in[1];
  const float* conv1_b  = (const float*)d_in[2];
  const float* loc_w    = (const float*)d_in[3];
  const float* loc_b    = (const float*)d_in[4];
  const float* score_w  = (const float*)d_in[5];
  const float* score_b  = (const float*)d_in[6];
  float* out = (float*)d_out;

  dim3 cgrid(7, 5, 8);
  conv3x3_relu<<<cgrid, 256>>>(x, conv1_w, conv1_b);
  rpn_head<<<475, 256>>>(loc_w, loc_b, score_w, score_b);
  fused_sort<<<8, 1024>>>();
  nms_mask<<<dim3(94, 47), 128>>>();
  nms_scan<<<1, 256>>>(out);
}

// round 13
// speedup vs baseline: 1.3585x; 1.0373x over previous
#include <cuda_runtime.h>

#define C_IN   512
#define IH     38
#define IW     50
#define HWPIX  1900
#define NANCH  17100
#define NSORT  32768
#define PRE_N  6000
#define POST_N 300
#define MASKW  94        // ceil(6000/64)

typedef unsigned long long ull;

// ---------------- device scratch (static, no allocation) ----------------
__device__ float    g_h1T[HWPIX * 512];                // conv output, [pixel][k]
__device__ float    g_box[NANCH * 4];                  // decoded clipped boxes
__device__ ull      g_keys[NSORT];                     // ping buffer
__device__ ull      g_keys2[NSORT];                    // pong buffer
__device__ float    g_tb[PRE_N * 4];                   // top-6000 boxes (sorted)
__device__ ull      g_mask[(size_t)PRE_N * MASKW];     // lower tri never written
__device__ ull      g_validw[96];                      // validity bits of top-6000
__device__ unsigned g_bar;                             // sort grid barrier

__constant__ float c_ab[9][4] = {
  {-37.254833f,  -82.50967f,   53.254833f,  98.50967f},
  {-82.50967f,  -173.01933f,   98.50967f,  189.01933f},
  {-173.01933f, -354.03867f,  189.01933f,  370.03867f},
  {-56.0f,       -56.0f,        72.0f,       72.0f},
  {-120.0f,     -120.0f,       136.0f,      136.0f},
  {-248.0f,     -248.0f,       264.0f,      264.0f},
  {-82.50967f,   -37.254833f,  98.50967f,   53.254833f},
  {-173.01933f,  -82.50967f,  189.01933f,   98.50967f},
  {-354.03867f, -173.01933f,  370.03867f,  189.01933f}};

// ---------------- f32x2 helpers ----------------
__device__ __forceinline__ ull dup2(float v) {
  ull r; asm("mov.b64 %0, {%1, %1};" : "=l"(r) : "f"(v)); return r;
}
__device__ __forceinline__ void fma2(ull& d, ull a, ull b) {
  asm("fma.rn.f32x2 %0, %1, %2, %0;" : "+l"(d) : "l"(a), "l"(b));
}
__device__ __forceinline__ float2 unpk(ull v) {
  float2 f; asm("mov.b64 {%0, %1}, %2;" : "=f"(f.x), "=f"(f.y) : "l"(v)); return f;
}

// ------- 3x3 conv + bias + relu, double-buffered + reg-staged prefetch --
__global__ __launch_bounds__(256) void conv3x3_relu(
    const float* __restrict__ x, const float* __restrict__ wgt,
    const float* __restrict__ bias) {
  const int wt = blockIdx.x;            // 0..6
  const int ht = blockIdx.y;            // 0..4
  const int kt = blockIdx.z;            // 0..7
  const int h0 = ht * 8, w0 = wt * 8;
  const int tid = threadIdx.x;
  const int ty  = tid >> 4;             // 0..15 (k groups of 4)
  const int txp = tid & 15;
  const int hh  = txp >> 1;             // 0..7
  const int wq  = txp & 1;              // 0..1 (w groups of 4)

  __shared__ float sW[2][72 * 66];                  // [buf][crs*66+k]
  __shared__ __align__(16) float sX[2][8][10][12];  // [buf][c][row][col]

  ull a00 = 0, a01 = 0, a02 = 0, a03 = 0;
  ull a10 = 0, a11 = 0, a12 = 0, a13 = 0;

  const int k0g = kt * 64;

  int wk[18], wcrs[18];
#pragma unroll
  for (int l = 0; l < 18; ++l) {
    int idx = tid + l * 256;            // = k*72 + crs
    wk[l] = idx / 72; wcrs[l] = idx % 72;
  }
  int xc[4], xrow[4], xcol[4];
  bool xon[4];
#pragma unroll
  for (int m = 0; m < 4; ++m) {
    int idx = tid + m * 256;
    xon[m] = idx < 800;
    int c = idx / 100, rem = idx % 100;
    xc[m] = c; xrow[m] = rem / 10; xcol[m] = rem % 10;
  }

  // prologue: fill buffer 0 for c0=0
  {
#pragma unroll
    for (int l = 0; l < 18; ++l)
      sW[0][wcrs[l] * 66 + wk[l]] =
          wgt[(size_t)(k0g + wk[l]) * 4608 + wcrs[l]];
#pragma unroll
    for (int m = 0; m < 4; ++m) {
      if (xon[m]) {
        int gh = h0 - 1 + xrow[m], gw = w0 - 1 + xcol[m];
        float v = 0.f;
        if (gh >= 0 && gh < IH && gw >= 0 && gw < IW)
          v = x[(size_t)xc[m] * HWPIX + gh * IW + gw];
        sX[0][xc[m]][xrow[m]][xcol[m]] = v;
      }
    }
  }
  __syncthreads();

  for (int c0 = 0; c0 < C_IN; c0 += 8) {
    const int cur = (c0 >> 3) & 1;
    const int nxt = cur ^ 1;
    const bool more = (c0 + 8) < C_IN;

    float wreg[18];
    float xreg[4];
    if (more) {
      const int c1 = c0 + 8;
#pragma unroll
      for (int l = 0; l < 18; ++l)
        wreg[l] = wgt[(size_t)(k0g + wk[l]) * 4608 + (size_t)c1 * 9 + wcrs[l]];
#pragma unroll
      for (int m = 0; m < 4; ++m) {
        float v = 0.f;
        if (xon[m]) {
          int gh = h0 - 1 + xrow[m], gw = w0 - 1 + xcol[m];
          if (gh >= 0 && gh < IH && gw >= 0 && gw < IW)
            v = x[(size_t)(c1 + xc[m]) * HWPIX + gh * IW + gw];
        }
        xreg[m] = v;
      }
    }

    const float* sWc = sW[cur];
#pragma unroll
    for (int c = 0; c < 8; ++c) {
#pragma unroll
      for (int r = 0; r < 3; ++r) {
        const float* xp = &sX[cur][c][hh + r][wq * 4];
        float4 xa = *(const float4*)xp;
        float2 xb = *(const float2*)(xp + 4);
        ull xd[6] = {dup2(xa.x), dup2(xa.y), dup2(xa.z),
                     dup2(xa.w), dup2(xb.x), dup2(xb.y)};
#pragma unroll
        for (int s = 0; s < 3; ++s) {
          int wi = (c * 9 + r * 3 + s) * 66 + ty * 4;
          ull w01 = *(const ull*)&sWc[wi];
          ull w23 = *(const ull*)&sWc[wi + 2];
          fma2(a00, w01, xd[s + 0]);
          fma2(a01, w01, xd[s + 1]);
          fma2(a02, w01, xd[s + 2]);
          fma2(a03, w01, xd[s + 3]);
          fma2(a10, w23, xd[s + 0]);
          fma2(a11, w23, xd[s + 1]);
          fma2(a12, w23, xd[s + 2]);
          fma2(a13, w23, xd[s + 3]);
        }
      }
    }

    if (more) {
#pragma unroll
      for (int l = 0; l < 18; ++l)
        sW[nxt][wcrs[l] * 66 + wk[l]] = wreg[l];
#pragma unroll
      for (int m = 0; m < 4; ++m)
        if (xon[m]) sX[nxt][xc[m]][xrow[m]][xcol[m]] = xreg[m];
    }
    __syncthreads();
  }

  const int h = h0 + hh;
  if (h < IH) {
    float b0 = bias[k0g + ty * 4 + 0];
    float b1 = bias[k0g + ty * 4 + 1];
    float b2 = bias[k0g + ty * 4 + 2];
    float b3 = bias[k0g + ty * 4 + 3];
    float2 p0[4] = {unpk(a00), unpk(a01), unpk(a02), unpk(a03)};
    float2 p1[4] = {unpk(a10), unpk(a11), unpk(a12), unpk(a13)};
#pragma unroll
    for (int j = 0; j < 4; ++j) {
      int ww = w0 + wq * 4 + j;
      if (ww < IW) {
        int p = h * IW + ww;
        float4 o;
        o.x = fmaxf(p0[j].x + b0, 0.f);
        o.y = fmaxf(p0[j].y + b1, 0.f);
        o.z = fmaxf(p1[j].x + b2, 0.f);
        o.w = fmaxf(p1[j].y + b3, 0.f);
        *(float4*)(&g_h1T[(size_t)p * 512 + k0g + ty * 4]) = o;
      }
    }
  }
}

// ------- 1x1 heads (4 pixels/block) + anchor decode + key build ---------
__device__ __forceinline__ unsigned f2key(float f) {
  unsigned u = __float_as_uint(f);
  return (u & 0x80000000u) ? ~u : (u | 0x80000000u);
}

__global__ __launch_bounds__(256) void rpn_head(
    const float* __restrict__ loc_w, const float* __restrict__ loc_b,
    const float* __restrict__ score_w, const float* __restrict__ score_b) {
  const int pb = blockIdx.x;            // 0..474 (4 pixels each)
  const int tid = threadIdx.x;
  if (pb == 0 && tid == 0) g_bar = 0u;  // reset grid barrier for fused_sort
  __shared__ float sh[4][512];
  __shared__ float sums[4][48];
  const int p0 = pb * 4;

#pragma unroll
  for (int m = 0; m < 4; ++m) {
    int idx = tid + m * 256;
    int px = idx >> 8, off = idx & 255;
    ((float2*)sh[px])[off] =
        ((const float2*)(g_h1T + (size_t)(p0 + px) * 512))[off];
  }
  __syncthreads();

  const int wid = tid >> 5, lane = tid & 31;
  for (int o = wid; o < 45; o += 8) {
    const float* wrow;
    float bb;
    if (o < 36) { wrow = loc_w + (size_t)o * 512; bb = loc_b[o]; }
    else { int a = o - 36; wrow = score_w + (size_t)(2 * a + 1) * 512; bb = score_b[2 * a + 1]; }
    float s0 = 0.f, s1 = 0.f, s2 = 0.f, s3 = 0.f;
#pragma unroll 4
    for (int c = lane; c < 512; c += 32) {
      float wv = wrow[c];
      s0 = fmaf(wv, sh[0][c], s0);
      s1 = fmaf(wv, sh[1][c], s1);
      s2 = fmaf(wv, sh[2][c], s2);
      s3 = fmaf(wv, sh[3][c], s3);
    }
#pragma unroll
    for (int off = 16; off; off >>= 1) {
      s0 += __shfl_down_sync(0xffffffffu, s0, off);
      s1 += __shfl_down_sync(0xffffffffu, s1, off);
      s2 += __shfl_down_sync(0xffffffffu, s2, off);
      s3 += __shfl_down_sync(0xffffffffu, s3, off);
    }
    if (lane == 0) {
      sums[0][o] = s0 + bb; sums[1][o] = s1 + bb;
      sums[2][o] = s2 + bb; sums[3][o] = s3 + bb;
    }
  }
  __syncthreads();

  if (tid < 36) {
    const int px = tid / 9, a = tid % 9;
    const int p = p0 + px;
    float dy = sums[px][a * 4 + 0], dx = sums[px][a * 4 + 1];
    float dh = sums[px][a * 4 + 2], dw = sums[px][a * 4 + 3];
    float fg = sums[px][36 + a];
    int h = p / IW, w = p % IW;
    float sy = (float)h * 16.f, sx = (float)w * 16.f;
    float ay0 = __fadd_rn(sy, c_ab[a][0]);
    float ax0 = __fadd_rn(sx, c_ab[a][1]);
    float ay1 = __fadd_rn(sy, c_ab[a][2]);
    float ax1 = __fadd_rn(sx, c_ab[a][3]);
    float ah = __fadd_rn(ay1, -ay0);
    float aw = __fadd_rn(ax1, -ax0);
    float acy = __fadd_rn(ay0, __fmul_rn(0.5f, ah));
    float acx = __fadd_rn(ax0, __fmul_rn(0.5f, aw));
    float cy = __fadd_rn(__fmul_rn(dy, ah), acy);
    float cx = __fadd_rn(__fmul_rn(dx, aw), acx);
    float bh = __fmul_rn(expf(dh), ah);
    float bw = __fmul_rn(expf(dw), aw);
    float y1 = fminf(fmaxf(__fadd_rn(cy, -__fmul_rn(0.5f, bh)), 0.f), 608.f);
    float x1 = fminf(fmaxf(__fadd_rn(cx, -__fmul_rn(0.5f, bw)), 0.f), 800.f);
    float y2 = fminf(fmaxf(__fadd_rn(cy,  __fmul_rn(0.5f, bh)), 0.f), 608.f);
    float x2 = fminf(fmaxf(__fadd_rn(cx,  __fmul_rn(0.5f, bw)), 0.f), 800.f);
    bool valid = (__fadd_rn(y2, -y1) >= 16.f) && (__fadd_rn(x2, -x1) >= 16.f);
    float sc = valid ? fg : -__int_as_float(0x7f800000);

    int i = p * 9 + a;
    g_box[i * 4 + 0] = y1; g_box[i * 4 + 1] = x1;
    g_box[i * 4 + 2] = y2; g_box[i * 4 + 3] = x2;
    g_keys[i] = ((ull)f2key(sc) << 32) | (ull)(~(unsigned)i);
  }
}

// ---- fused bitonic sort: 4 regs/thread, smem only for j>=128 -----------
__device__ __forceinline__ void grid_sync8(unsigned& target) {
  __syncthreads();
  target += 8;
  if (threadIdx.x == 0) {
    __threadfence();
    atomicAdd(&g_bar, 1u);
    while (atomicAdd(&g_bar, 0u) < target) {}
    __threadfence();
  }
  __syncthreads();
}

// register compare-exchange via shfl_xor
#define RCE(e, j, keepMax) do {                                        \
    ull _p = __shfl_xor_sync(0xffffffffu, (e), (j));                   \
    (e) = (keepMax) ? ((e) > _p ? (e) : _p) : ((e) < _p ? (e) : _p);   \
  } while (0)

// in-thread pair swap: lower element ea keeps max iff desc
#define SWAP2(ea, eb, desc) do {                                       \
    ull _hi = (ea) > (eb) ? (ea) : (eb);                               \
    ull _lo = (ea) > (eb) ? (eb) : (ea);                               \
    if (desc) { (ea) = _hi; (eb) = _lo; }                              \
    else      { (ea) = _lo; (eb) = _hi; }                              \
  } while (0)

// stages j = jstart..1 fully in registers (jstart in {1,...,64})
// lane holds elements i0=128w+l, i1=i0+32, i2=i0+64, i3=i0+96
#define REG_STAGES(jstart, kk) do {                                    \
    const bool d0 = ((i0 & (kk)) == 0);                                \
    const bool d1 = ((i1 & (kk)) == 0);                                \
    const bool d2 = ((i2 & (kk)) == 0);                                \
    const bool d3 = ((i3 & (kk)) == 0);                                \
    if ((jstart) >= 64) { SWAP2(e0, e2, d0); SWAP2(e1, e3, d1); }      \
    if ((jstart) >= 32) { SWAP2(e0, e1, d0); SWAP2(e2, e3, d2); }      \
    if ((jstart) >= 16) {                                              \
      RCE(e0, 16, d0 ^ ((lane & 16) != 0));                            \
      RCE(e1, 16, d1 ^ ((lane & 16) != 0));                            \
      RCE(e2, 16, d2 ^ ((lane & 16) != 0));                            \
      RCE(e3, 16, d3 ^ ((lane & 16) != 0));                            \
    }                                                                  \
    if ((jstart) >= 8) {                                               \
      RCE(e0, 8, d0 ^ ((lane & 8) != 0));                              \
      RCE(e1, 8, d1 ^ ((lane & 8) != 0));                              \
      RCE(e2, 8, d2 ^ ((lane & 8) != 0));                              \
      RCE(e3, 8, d3 ^ ((lane & 8) != 0));                              \
    }                                                                  \
    if ((jstart) >= 4) {                                               \
      RCE(e0, 4, d0 ^ ((lane & 4) != 0));                              \
      RCE(e1, 4, d1 ^ ((lane & 4) != 0));                              \
      RCE(e2, 4, d2 ^ ((lane & 4) != 0));                              \
      RCE(e3, 4, d3 ^ ((lane & 4) != 0));                              \
    }                                                                  \
    if ((jstart) >= 2) {                                               \
      RCE(e0, 2, d0 ^ ((lane & 2) != 0));                              \
      RCE(e1, 2, d1 ^ ((lane & 2) != 0));                              \
      RCE(e2, 2, d2 ^ ((lane & 2) != 0));                              \
      RCE(e3, 2, d3 ^ ((lane & 2) != 0));                              \
    }                                                                  \
    RCE(e0, 1, d0 ^ ((lane & 1) != 0));                                \
    RCE(e1, 1, d1 ^ ((lane & 1) != 0));                                \
    RCE(e2, 1, d2 ^ ((lane & 1) != 0));                                \
    RCE(e3, 1, d3 ^ ((lane & 1) != 0));                                \
  } while (0)

// smem stages j = jstart..128, registers in/out
#define SMEM_STAGES(jstart, kk) do {                                   \
    s[i0 - base] = e0; s[i1 - base] = e1;                              \
    s[i2 - base] = e2; s[i3 - base] = e3;                              \
    __syncthreads();                                                   \
    for (int j = (jstart); j >= 128; j >>= 1) {                        \
      _Pragma("unroll")                                                \
      for (int m = 0; m < 2; ++m) {                                    \
        int tt = t + m * 1024;                                         \
        int i = ((tt & ~(j - 1)) << 1) | (tt & (j - 1));               \
        int ix = i | j;                                                \
        bool dsc = (((base + i) & (kk)) == 0);                         \
        ull a = s[i], b = s[ix];                                       \
        if (dsc ? (a < b) : (a > b)) { s[i] = b; s[ix] = a; }          \
      }                                                                \
      __syncthreads();                                                 \
    }                                                                  \
    e0 = s[i0 - base]; e1 = s[i1 - base];                              \
    e2 = s[i2 - base]; e3 = s[i3 - base];                              \
  } while (0)

#define STORE_REG(buf) do {                                            \
    (buf)[i0] = e0; (buf)[i1] = e1; (buf)[i2] = e2; (buf)[i3] = e3;    \
  } while (0)

#define COMBINE_REG(buf, K, J) do {                                    \
    bool lower = ((base & (J)) == 0);                                  \
    bool dC = ((base & (K)) == 0);                                     \
    bool tM = (lower == dC);                                           \
    ull v0 = __ldcg(&(buf)[i0 ^ (J)]);                                 \
    ull v1 = __ldcg(&(buf)[i1 ^ (J)]);                                 \
    ull v2 = __ldcg(&(buf)[i2 ^ (J)]);                                 \
    ull v3 = __ldcg(&(buf)[i3 ^ (J)]);                                 \
    e0 = tM ? (e0 > v0 ? e0 : v0) : (e0 < v0 ? e0 : v0);               \
    e1 = tM ? (e1 > v1 ? e1 : v1) : (e1 < v1 ? e1 : v1);               \
    e2 = tM ? (e2 > v2 ? e2 : v2) : (e2 < v2 ? e2 : v2);               \
    e3 = tM ? (e3 > v3 ? e3 : v3) : (e3 < v3 ? e3 : v3);               \
  } while (0)

#define TAIL_REG(K) do { SMEM_STAGES(2048, K); REG_STAGES(64, K); } while (0)

__global__ __launch_bounds__(1024) void fused_sort() {
  __shared__ ull s[4096];
  const int base = blockIdx.x * 4096;
  const int t = threadIdx.x;
  const int lane = t & 31;
  const int wrp = t >> 5;
  const int i0 = base + wrp * 128 + lane;   // global element ids
  const int i1 = i0 + 32;
  const int i2 = i0 + 64;
  const int i3 = i0 + 96;
  unsigned bar_t = 0;

  ull e0 = (i0 < NANCH) ? g_keys[i0] : 0ull;
  ull e1 = (i1 < NANCH) ? g_keys[i1] : 0ull;
  ull e2 = (i2 < NANCH) ? g_keys[i2] : 0ull;
  ull e3 = (i3 < NANCH) ? g_keys[i3] : 0ull;

  // local sort k = 2..128: fully in registers, zero barriers
  REG_STAGES(1, 2);
  REG_STAGES(2, 4);
  REG_STAGES(4, 8);
  REG_STAGES(8, 16);
  REG_STAGES(16, 32);
  REG_STAGES(32, 64);
  REG_STAGES(64, 128);
  // k = 256..4096: smem for j>=128, registers for j<=64
  SMEM_STAGES(128, 256);   REG_STAGES(64, 256);
  SMEM_STAGES(256, 512);   REG_STAGES(64, 512);
  SMEM_STAGES(512, 1024);  REG_STAGES(64, 1024);
  SMEM_STAGES(1024, 2048); REG_STAGES(64, 2048);
  SMEM_STAGES(2048, 4096); REG_STAGES(64, 4096);

  STORE_REG(g_keys);  grid_sync8(bar_t);
  COMBINE_REG(g_keys, 8192, 4096);  TAIL_REG(8192);

  STORE_REG(g_keys2); grid_sync8(bar_t);
  COMBINE_REG(g_keys2, 16384, 8192);

  STORE_REG(g_keys);  grid_sync8(bar_t);
  COMBINE_REG(g_keys, 16384, 4096); TAIL_REG(16384);

  STORE_REG(g_keys2); grid_sync8(bar_t);
  COMBINE_REG(g_keys2, 32768, 16384);

  STORE_REG(g_keys);  grid_sync8(bar_t);
  COMBINE_REG(g_keys, 32768, 8192);

  STORE_REG(g_keys2); grid_sync8(bar_t);

  // only blocks covering e < 8192 matter from here on
  if (base < 8192) {
    COMBINE_REG(g_keys2, 32768, 4096); TAIL_REG(32768);
    // epilogue from registers: validity ballots + box gather
    bool v0 = (i0 < PRE_N) && ((unsigned)(e0 >> 32) > 0x007FFFFFu);
    bool v1 = (i1 < PRE_N) && ((unsigned)(e1 >> 32) > 0x007FFFFFu);
    bool v2 = (i2 < PRE_N) && ((unsigned)(e2 >> 32) > 0x007FFFFFu);
    bool v3 = (i3 < PRE_N) && ((unsigned)(e3 >> 32) > 0x007FFFFFu);
    unsigned b0 = __ballot_sync(0xffffffffu, v0);
    unsigned b1 = __ballot_sync(0xffffffffu, v1);
    unsigned b2 = __ballot_sync(0xffffffffu, v2);
    unsigned b3 = __ballot_sync(0xffffffffu, v3);
    if (i0 < 6144) {                 // warp-uniform (128-elem aligned spans)
      if (lane == 0) {
        ((unsigned*)g_validw)[i0 >> 5] = b0;
        ((unsigned*)g_validw)[i1 >> 5] = b1;
        ((unsigned*)g_validw)[i2 >> 5] = b2;
        ((unsigned*)g_validw)[i3 >> 5] = b3;
      }
      if (i0 < PRE_N) {
        unsigned idx = ~(unsigned)(e0 & 0xffffffffull);
        float4 b = make_float4(0.f, 0.f, 0.f, 0.f);
        if (idx < NANCH) b = ((const float4*)g_box)[idx];
        ((float4*)g_tb)[i0] = b;
      }
      if (i1 < PRE_N) {
        unsigned idx = ~(unsigned)(e1 & 0xffffffffull);
        float4 b = make_float4(0.f, 0.f, 0.f, 0.f);
        if (idx < NANCH) b = ((const float4*)g_box)[idx];
        ((float4*)g_tb)[i1] = b;
      }
      if (i2 < PRE_N) {
        unsigned idx = ~(unsigned)(e2 & 0xffffffffull);
        float4 b = make_float4(0.f, 0.f, 0.f, 0.f);
        if (idx < NANCH) b = ((const float4*)g_box)[idx];
        ((float4*)g_tb)[i2] = b;
      }
      if (i3 < PRE_N) {
        unsigned idx = ~(unsigned)(e3 & 0xffffffffull);
        float4 b = make_float4(0.f, 0.f, 0.f, 0.f);
        if (idx < NANCH) b = ((const float4*)g_box)[idx];
        ((float4*)g_tb)[i3] = b;
      }
    }
  }
}

// ------- NMS mask: 128-row x 64-col tiles, fully unrolled inner ---------
__global__ __launch_bounds__(128) void nms_mask() {
  const int cb = blockIdx.x;      // 0..93
  const int rb = blockIdx.y;      // 0..46
  if (cb < 2 * rb) return;
  const int tid = threadIdx.x;
  __shared__ float4 colb[64];
  __shared__ float cola[64];
  const int j0 = cb * 64;
  if (tid < 64) {
    int jj = j0 + tid;
    float4 b = (jj < PRE_N) ? ((const float4*)g_tb)[jj]
                            : make_float4(0.f, 0.f, 0.f, 0.f);
    colb[tid] = b;
    cola[tid] = __fmul_rn(__fadd_rn(b.z, -b.x), __fadd_rn(b.w, -b.y));
  }
  __syncthreads();
  const int i = rb * 128 + tid;
  if (i >= PRE_N) return;
  if (i >= j0 + 64) return;
  float4 r = ((const float4*)g_tb)[i];
  float ra = __fmul_rn(__fadd_rn(r.z, -r.x), __fadd_rn(r.w, -r.y));
  ull bits = 0ull;
#pragma unroll
  for (int q = 0; q < 64; ++q) {
    float4 c = colb[q];
    float ty1 = fmaxf(r.x, c.x);
    float tx1 = fmaxf(r.y, c.y);
    float ty2 = fminf(r.z, c.z);
    float tx2 = fminf(r.w, c.w);
    float ihh = fmaxf(__fadd_rn(ty2, -ty1), 0.f);
    float iww = fmaxf(__fadd_rn(tx2, -tx1), 0.f);
    float inter = __fmul_rn(ihh, iww);
    float uni = fmaxf(__fadd_rn(__fadd_rn(ra, cola[q]), -inter), 1e-9f);
    float d = __fmaf_rn(-0.7f, uni, inter);
    bool sup;
    if (fabsf(d) < 3e-5f * uni)
      sup = (__fdiv_rn(inter, uni) > 0.7f);
    else
      sup = d > 0.f;
    if (sup) bits |= (1ull << q);
  }
  if (j0 <= i) {
    int dq = i - j0;
    bits = (dq >= 63) ? 0ull : (bits & (~0ull << (dq + 1)));
  }
  g_mask[(size_t)i * MASKW + cb] = bits;
}

// ---- NMS scan: ffs bit-walk + parallel row fold, early stop @300 -------
__global__ __launch_bounds__(256) void nms_scan(float* __restrict__ out) {
  __shared__ ull remv[MASKW];
  __shared__ int keptIdx[POST_N];
  __shared__ int wordKept[64];
  __shared__ int s_nk, s_nwk;
  const int tid = threadIdx.x;
  if (tid < MASKW) remv[tid] = 0ull;
  if (tid == 0) s_nk = 0;
  for (int i = tid; i < POST_N * 4; i += 256) out[i] = 0.f;
  __syncthreads();

  for (int w = 0; w < MASKW; ++w) {
    if (tid < 32) {
      ull vw = g_validw[w];
      ull alive = vw & ~remv[w];
      int base = w * 64;
      ull mA = ((alive >> tid) & 1ull) ? g_mask[(size_t)(base + tid) * MASKW + w] : 0ull;
      ull mB = ((alive >> (tid + 32)) & 1ull) ? g_mask[(size_t)(base + tid + 32) * MASKW + w] : 0ull;
      int nk = s_nk, nwk = 0;
      while (alive && nk < POST_N) {
        int q = __ffsll((long long)alive) - 1;
        ull mq = (q < 32) ? __shfl_sync(0xffffffffu, mA, q)
                          : __shfl_sync(0xffffffffu, mB, q - 32);
        if (tid == 0) { keptIdx[nk] = base + q; wordKept[nwk] = base + q; }
        ++nk; ++nwk;
        alive &= ~((1ull << q) | mq);
      }
      if (tid == 0) { s_nk = nk; s_nwk = nwk; }
    }
    __syncthreads();
    if (s_nwk > 0) {
      int total = s_nwk * MASKW;
      for (int e = tid; e < total; e += 256) {
        int r = e / MASKW, wd = e - r * MASKW;
        ull m = g_mask[(size_t)wordKept[r] * MASKW + wd];
        if (m) atomicOr(&remv[wd], m);
      }
      __syncthreads();
    }
    if (s_nk >= POST_N) break;
  }

  __syncthreads();
  for (int r = tid; r < s_nk; r += 256)
    ((float4*)out)[r] = ((const float4*)g_tb)[keptIdx[r]];
}

// ---------------- launcher ----------------
extern "C" void kernel_launch(void* const* d_in, const int* in_sizes, int n_in,
                              void* d_out, int out_size) {
  const float* x        = (const float*)d_in[0];
  const float* conv1_w  = (const float*)d_in[1];
  const float* conv1_b  = (const float*)d_in[2];
  const float* loc_w    = (const float*)d_in[3];
  const float* loc_b    = (const float*)d_in[4];
  const float* score_w  = (const float*)d_in[5];
  const float* score_b  = (const float*)d_in[6];
  float* out = (float*)d_out;

  dim3 cgrid(7, 5, 8);
  conv3x3_relu<<<cgrid, 256>>>(x, conv1_w, conv1_b);
  rpn_head<<<475, 256>>>(loc_w, loc_b, score_w, score_b);
  fused_sort<<<8, 1024>>>();
  nms_mask<<<dim3(94, 47), 128>>>();
  nms_scan<<<1, 256>>>(out);
}